// round 1
// baseline (speedup 1.0000x reference)
#include <cuda_runtime.h>
#include <stdint.h>

#define N_DET 1024
#define HW 40960
#define W64 640          // u64 words per mask row
#define W32 1280         // u32 words per mask row
#define SIGMA 2.0f
#define TI 16            // 64-row tiles per dim (1024/64)
#define KC 16            // u64 words per K-chunk

// Scratch (device globals — no allocation allowed)
__device__ unsigned long long g_packed[N_DET * W64];   // 5.24 MB bit-packed masks
__device__ float g_sum[N_DET];                          // sum_masks
__device__ float g_decay[N_DET * N_DET];                // decay_iou, valid for i<j only
__device__ float g_comp2[N_DET];                        // compensate_iou^2 per row

// ---------------------------------------------------------------------------
// Kernel 1: pack binary fp32 masks into bitmasks via warp ballot; also sum.
// grid = N_DET blocks, 256 threads. Coalesced fp32 reads, HBM-bound.
// ---------------------------------------------------------------------------
__global__ void pack_kernel(const float* __restrict__ seg) {
    int r    = blockIdx.x;
    int tid  = threadIdx.x;
    int lane = tid & 31;
    int wid  = tid >> 5;

    const float* row = seg + (size_t)r * HW;
    unsigned* out32 = (unsigned*)(g_packed + (size_t)r * W64);

    int cnt = 0;
    #pragma unroll 4
    for (int it = 0; it < HW / 256; ++it) {
        float v = row[it * 256 + tid];
        unsigned ballot = __ballot_sync(0xFFFFFFFFu, v != 0.0f);
        if (lane == 0) {
            out32[it * 8 + wid] = ballot;
            cnt += __popc(ballot);
        }
    }

    __shared__ int s[8];
    if (lane == 0) s[wid] = cnt;
    __syncthreads();
    if (tid == 0) {
        int t = 0;
        #pragma unroll
        for (int w = 0; w < 8; ++w) t += s[w];
        g_sum[r] = (float)t;
    }
}

// ---------------------------------------------------------------------------
// Kernel 2: pairwise intersection via AND+popcount, 64x64 tile per block,
// upper-triangular tile grid (136 blocks). Writes decay_iou for i<j.
// 256 threads = 16x16, each thread computes a 4x4 strided pair sub-block.
// smem row stride KC+1=17 u64 -> conflict-free strided LDS.64 for B rows.
// ---------------------------------------------------------------------------
__global__ void __launch_bounds__(256, 1) pair_kernel(const int* __restrict__ labels) {
    // Map linear block id -> (ti, tj) with ti <= tj
    int b = blockIdx.x;
    int ti = 0;
    while (b >= TI - ti) { b -= TI - ti; ++ti; }
    int tj = ti + b;

    __shared__ unsigned long long sA[64][KC + 1];
    __shared__ unsigned long long sB[64][KC + 1];

    int tid = threadIdx.x;
    int tx = tid & 15;   // column group
    int ty = tid >> 4;   // row group

    unsigned acc[4][4];
    #pragma unroll
    for (int u = 0; u < 4; ++u)
        #pragma unroll
        for (int v = 0; v < 4; ++v) acc[u][v] = 0u;

    const unsigned long long* baseA = g_packed + (size_t)(ti * 64) * W64;
    const unsigned long long* baseB = g_packed + (size_t)(tj * 64) * W64;

    for (int k0 = 0; k0 < W64; k0 += KC) {
        // Stage chunk: 64 rows x KC u64 per side, 4 u64 per thread per side
        #pragma unroll
        for (int q = 0; q < 4; ++q) {
            int l = tid + q * 256;
            int r = l >> 4;
            int k = l & 15;
            sA[r][k] = baseA[(size_t)r * W64 + k0 + k];
            sB[r][k] = baseB[(size_t)r * W64 + k0 + k];
        }
        __syncthreads();

        #pragma unroll
        for (int k = 0; k < KC; ++k) {
            unsigned long long a[4], bb[4];
            #pragma unroll
            for (int u = 0; u < 4; ++u) a[u] = sA[ty + 16 * u][k];
            #pragma unroll
            for (int v = 0; v < 4; ++v) bb[v] = sB[tx + 16 * v][k];
            #pragma unroll
            for (int u = 0; u < 4; ++u)
                #pragma unroll
                for (int v = 0; v < 4; ++v)
                    acc[u][v] += (unsigned)__popcll(a[u] & bb[v]);
        }
        __syncthreads();
    }

    // Epilogue: decay_iou[i][j] = (labels match && i<j) ? inter/union : 0
    #pragma unroll
    for (int u = 0; u < 4; ++u) {
        int i = ti * 64 + ty + 16 * u;
        float si = g_sum[i];
        int li = labels[i];
        #pragma unroll
        for (int v = 0; v < 4; ++v) {
            int j = tj * 64 + tx + 16 * v;
            if (i < j) {
                float d = 0.0f;
                if (li == labels[j]) {
                    float inter = (float)acc[u][v];
                    float uni = si + g_sum[j] - inter;
                    d = inter / uni;
                }
                g_decay[(size_t)i * N_DET + j] = d;
            }
        }
    }
}

// ---------------------------------------------------------------------------
// Kernel 3: compensate_iou[j] = max_{i<j} decay_iou[i][j]; store its square.
// ---------------------------------------------------------------------------
__global__ void colmax_kernel() {
    int j = blockIdx.x;
    int tid = threadIdx.x;
    float m = 0.0f;   // triu column max includes zeros
    for (int i = tid; i < j; i += 256)
        m = fmaxf(m, g_decay[(size_t)i * N_DET + j]);

    __shared__ float s[256];
    s[tid] = m;
    __syncthreads();
    for (int o = 128; o > 0; o >>= 1) {
        if (tid < o) s[tid] = fmaxf(s[tid], s[tid + o]);
        __syncthreads();
    }
    if (tid == 0) g_comp2[j] = s[0] * s[0];
}

// ---------------------------------------------------------------------------
// Kernel 4: out[j] = score[j] * exp(-SIGMA * max_i(d_ij^2 - c_i^2))
// (min over i of exp ratio == exp of -sigma * max, by monotonicity)
// ---------------------------------------------------------------------------
__global__ void final_kernel(const float* __restrict__ scores,
                             float* __restrict__ out) {
    int j = blockIdx.x;
    int tid = threadIdx.x;
    float m = -1e30f;
    for (int i = tid; i < N_DET; i += 256) {
        float d = (i < j) ? g_decay[(size_t)i * N_DET + j] : 0.0f;
        m = fmaxf(m, d * d - g_comp2[i]);
    }
    __shared__ float s[256];
    s[tid] = m;
    __syncthreads();
    for (int o = 128; o > 0; o >>= 1) {
        if (tid < o) s[tid] = fmaxf(s[tid], s[tid + o]);
        __syncthreads();
    }
    if (tid == 0) out[j] = scores[j] * expf(-SIGMA * s[0]);
}

// ---------------------------------------------------------------------------
extern "C" void kernel_launch(void* const* d_in, const int* in_sizes, int n_in,
                              void* d_out, int out_size) {
    const float* seg    = (const float*)d_in[0];
    const int*   labels = (const int*)d_in[1];
    const float* scores = (const float*)d_in[2];
    float* out = (float*)d_out;

    pack_kernel<<<N_DET, 256>>>(seg);
    pair_kernel<<<TI * (TI + 1) / 2, 256>>>(labels);
    colmax_kernel<<<N_DET, 256>>>();
    final_kernel<<<N_DET, 256>>>(scores, out);
}

// round 3
// speedup vs baseline: 1.7691x; 1.7691x over previous
#include <cuda_runtime.h>
#include <stdint.h>

#define N_DET 1024
#define HW 40960
#define SIGMA 2.0f
#define KSPLIT 4
#define NT 8                 // 128-row tile grid
#define NTILES 36            // triu incl diag
#define STAGES 4
#define KC_BYTES 128         // s8 per row per chunk
#define NC ((HW / KSPLIT) / KC_BYTES)   // 80 chunks per CTA
#define ROW_STRIDE 144       // 128 + 16B pad -> conflict-free ldmatrix
#define SIDE_BYTES (128 * ROW_STRIDE)   // 18432
#define STAGE_BYTES (2 * SIDE_BYTES)    // 36864 (A then B)
#define SMEM_TOTAL (STAGES * STAGE_BYTES)  // 147456

// ---- device scratch (no runtime allocation allowed) ----
__device__ __align__(16) signed char g_s8[(size_t)N_DET * HW];   // 40 MB
__device__ float g_sum[N_DET];
__device__ float g_part[KSPLIT][(size_t)N_DET * N_DET];          // 16 MB
__device__ float g_decay[(size_t)N_DET * N_DET];                 // 4 MB
__device__ float g_comp2[N_DET];

// ---------------------------------------------------------------------------
// portable PTX helpers (plain sm_100 target OK)
// ---------------------------------------------------------------------------
__device__ __forceinline__ uint32_t smem_u32(const void* p) {
    uint32_t a;
    asm("{ .reg .u64 t; cvta.to.shared.u64 t, %1; cvt.u32.u64 %0, t; }" : "=r"(a) : "l"(p));
    return a;
}
#define CP_ASYNC16(dst, src) \
    asm volatile("cp.async.cg.shared.global [%0], [%1], 16;" :: "r"((uint32_t)(dst)), "l"(src) : "memory")
#define CP_COMMIT() asm volatile("cp.async.commit_group;" ::: "memory")
#define CP_WAIT3()  asm volatile("cp.async.wait_group 3;" ::: "memory")

#define LDSM_X4(r0, r1, r2, r3, addr) \
    asm volatile("ldmatrix.sync.aligned.m8n8.x4.shared.b16 {%0,%1,%2,%3}, [%4];" \
        : "=r"(r0), "=r"(r1), "=r"(r2), "=r"(r3) : "r"(addr))
#define LDSM_X2(r0, r1, addr) \
    asm volatile("ldmatrix.sync.aligned.m8n8.x2.shared.b16 {%0,%1}, [%2];" \
        : "=r"(r0), "=r"(r1) : "r"(addr))
#define MMA_S8(d, a, b) \
    asm volatile("mma.sync.aligned.m16n8k32.row.col.s32.s8.s8.s32 " \
        "{%0,%1,%2,%3}, {%4,%5,%6,%7}, {%8,%9}, {%0,%1,%2,%3};" \
        : "+r"((d)[0]), "+r"((d)[1]), "+r"((d)[2]), "+r"((d)[3]) \
        : "r"((a)[0]), "r"((a)[1]), "r"((a)[2]), "r"((a)[3]), "r"((b)[0]), "r"((b)[1]))

// ---------------------------------------------------------------------------
// Kernel 1: fp32 {0,1} -> s8 {0,1} + row sums
// ---------------------------------------------------------------------------
__global__ void convert_kernel(const float* __restrict__ seg) {
    int r = blockIdx.x, tid = threadIdx.x;
    const float4* in4 = (const float4*)(seg + (size_t)r * HW);
    uint4* out = (uint4*)(g_s8 + (size_t)r * HW);
    int cnt = 0;
    #pragma unroll
    for (int it = 0; it < HW / 4096; ++it) {       // 10 iters
        uint32_t w[4];
        #pragma unroll
        for (int q = 0; q < 4; ++q) {
            float4 f = in4[it * 1024 + tid * 4 + q];
            uint32_t b0 = (f.x != 0.0f), b1 = (f.y != 0.0f),
                     b2 = (f.z != 0.0f), b3 = (f.w != 0.0f);
            cnt += b0 + b1 + b2 + b3;
            w[q] = b0 | (b1 << 8) | (b2 << 16) | (b3 << 24);
        }
        out[it * 256 + tid] = make_uint4(w[0], w[1], w[2], w[3]);
    }
    #pragma unroll
    for (int o = 16; o; o >>= 1) cnt += __shfl_xor_sync(0xFFFFFFFFu, cnt, o);
    __shared__ int s[8];
    if ((tid & 31) == 0) s[tid >> 5] = cnt;
    __syncthreads();
    if (tid == 0) {
        int t = 0;
        #pragma unroll
        for (int w = 0; w < 8; ++w) t += s[w];
        g_sum[r] = (float)t;
    }
}

// ---------------------------------------------------------------------------
// Kernel 2: s8 mma.sync GEMM. 128x128 tile/CTA, K-split 4, 4-stage cp.async.
// 8 warps; warp tile 64x32 via m16n8k32 (4x4 mma grid).
// ---------------------------------------------------------------------------
__global__ void __launch_bounds__(256, 1) gemm_kernel() {
    extern __shared__ char smem[];
    uint32_t sbase = smem_u32(smem);
    int tid = threadIdx.x;
    int wid = tid >> 5;
    int lane = tid & 31;

    // tile decode: blockIdx -> (ti, tj, ks), ti <= tj
    int bx = blockIdx.x;
    int ks = bx % KSPLIT;
    int t = bx / KSPLIT;
    int ti = 0;
    while (t >= NT - ti) { t -= NT - ti; ++ti; }
    int tj = ti + t;

    // cp.async addressing: granule l = tid + q*256 -> row = l>>3, g = l&7
    const char* srcA[4];
    const char* srcB[4];
    uint32_t dstoff[4];
    #pragma unroll
    for (int q = 0; q < 4; ++q) {
        int l = tid + q * 256;
        int row = l >> 3, g = l & 7;
        size_t kbase = (size_t)ks * (HW / KSPLIT) + (size_t)g * 16;
        srcA[q] = (const char*)g_s8 + (size_t)(ti * 128 + row) * HW + kbase;
        srcB[q] = (const char*)g_s8 + (size_t)(tj * 128 + row) * HW + kbase;
        dstoff[q] = (uint32_t)(row * ROW_STRIDE + g * 16);
    }

    // prologue: fill 3 stages
    #pragma unroll
    for (int p = 0; p < STAGES - 1; ++p) {
        uint32_t ab = sbase + p * STAGE_BYTES;
        uint32_t bb = ab + SIDE_BYTES;
        size_t cb = (size_t)p * KC_BYTES;
        #pragma unroll
        for (int q = 0; q < 4; ++q) {
            CP_ASYNC16(ab + dstoff[q], srcA[q] + cb);
            CP_ASYNC16(bb + dstoff[q], srcB[q] + cb);
        }
        CP_COMMIT();
    }

    // ldmatrix per-lane address bases (stage 0)
    int wm = wid & 1;          // row half (64 rows)
    int wn = wid >> 1;         // col quarter (32 cols)
    int mi = lane >> 3, lr = lane & 7;
    // A x4: matrix mi -> row += (mi&1)*8, kbyte += (mi>>1)*16
    uint32_t a_base = sbase + (uint32_t)((wm * 64 + (mi & 1) * 8 + lr) * ROW_STRIDE + (mi >> 1) * 16);
    // B x2: lanes 0-15 meaningful; half = (lane>>3)&1 selects k 0-15 / 16-31
    uint32_t b_base = sbase + SIDE_BYTES
                    + (uint32_t)((wn * 32 + (lane & 7)) * ROW_STRIDE + ((lane >> 3) & 1) * 16);

    int acc[4][4][4];
    #pragma unroll
    for (int mb = 0; mb < 4; ++mb)
        #pragma unroll
        for (int nb = 0; nb < 4; ++nb)
            #pragma unroll
            for (int c = 0; c < 4; ++c) acc[mb][nb][c] = 0;

    for (int jm = 0; jm < NC; ++jm) {
        // issue chunk jm+3 into stage (jm+3)%4
        int nxt = jm + STAGES - 1;
        if (nxt < NC) {
            uint32_t ab = sbase + (nxt & 3) * STAGE_BYTES;
            uint32_t bb = ab + SIDE_BYTES;
            size_t cb = (size_t)nxt * KC_BYTES;
            #pragma unroll
            for (int q = 0; q < 4; ++q) {
                CP_ASYNC16(ab + dstoff[q], srcA[q] + cb);
                CP_ASYNC16(bb + dstoff[q], srcB[q] + cb);
            }
        }
        CP_COMMIT();
        CP_WAIT3();            // chunk jm resident
        __syncthreads();

        uint32_t soff = (jm & 3) * STAGE_BYTES;
        #pragma unroll
        for (int ksb = 0; ksb < 4; ++ksb) {    // 4 x k32 per 128B chunk
            uint32_t k0 = ksb * 32;
            uint32_t a[4][4], b[4][2];
            #pragma unroll
            for (int mb = 0; mb < 4; ++mb)
                LDSM_X4(a[mb][0], a[mb][1], a[mb][2], a[mb][3],
                        a_base + soff + mb * (16 * ROW_STRIDE) + k0);
            #pragma unroll
            for (int nb = 0; nb < 4; ++nb)
                LDSM_X2(b[nb][0], b[nb][1],
                        b_base + soff + nb * (8 * ROW_STRIDE) + k0);
            #pragma unroll
            for (int mb = 0; mb < 4; ++mb)
                #pragma unroll
                for (int nb = 0; nb < 4; ++nb)
                    MMA_S8(acc[mb][nb], a[mb], b[nb]);
        }
        __syncthreads();       // protect stage before rewrite next iter
    }

    // epilogue: write partial intersections as float
    float* part = g_part[ks];
    #pragma unroll
    for (int mb = 0; mb < 4; ++mb) {
        int r0 = ti * 128 + wm * 64 + mb * 16 + (lane >> 2);
        #pragma unroll
        for (int nb = 0; nb < 4; ++nb) {
            int c = tj * 128 + wn * 32 + nb * 8 + (lane & 3) * 2;
            float2 v0 = make_float2((float)acc[mb][nb][0], (float)acc[mb][nb][1]);
            float2 v1 = make_float2((float)acc[mb][nb][2], (float)acc[mb][nb][3]);
            *(float2*)(part + (size_t)r0 * N_DET + c) = v0;
            *(float2*)(part + (size_t)(r0 + 8) * N_DET + c) = v1;
        }
    }
}

// ---------------------------------------------------------------------------
// Kernel 3: combine K-split partials -> decay_iou
// ---------------------------------------------------------------------------
__global__ void decay_kernel(const int* __restrict__ labels) {
    int i = blockIdx.x, tid = threadIdx.x;
    float si = g_sum[i];
    int li = labels[i];
    for (int j = tid; j < N_DET; j += 256) {
        if (j > i) {
            size_t idx = (size_t)i * N_DET + j;
            float inter = g_part[0][idx] + g_part[1][idx] + g_part[2][idx] + g_part[3][idx];
            float d = 0.0f;
            if (li == labels[j]) d = inter / (si + g_sum[j] - inter);
            g_decay[idx] = d;
        }
    }
}

// ---------------------------------------------------------------------------
// Kernel 4: compensate_iou[j] = max_{i<j} decay[i][j]; store square
// ---------------------------------------------------------------------------
__global__ void colmax_kernel() {
    int j = blockIdx.x, tid = threadIdx.x;
    float m = 0.0f;
    for (int i = tid; i < j; i += 256)
        m = fmaxf(m, g_decay[(size_t)i * N_DET + j]);
    __shared__ float s[256];
    s[tid] = m;
    __syncthreads();
    for (int o = 128; o > 0; o >>= 1) {
        if (tid < o) s[tid] = fmaxf(s[tid], s[tid + o]);
        __syncthreads();
    }
    if (tid == 0) g_comp2[j] = s[0] * s[0];
}

// ---------------------------------------------------------------------------
// Kernel 5: out[j] = score[j] * exp(-SIGMA * max_i(d_ij^2 - c_i^2))
// ---------------------------------------------------------------------------
__global__ void final_kernel(const float* __restrict__ scores, float* __restrict__ out) {
    int j = blockIdx.x, tid = threadIdx.x;
    float m = -1e30f;
    for (int i = tid; i < N_DET; i += 256) {
        float d = (i < j) ? g_decay[(size_t)i * N_DET + j] : 0.0f;
        m = fmaxf(m, d * d - g_comp2[i]);
    }
    __shared__ float s[256];
    s[tid] = m;
    __syncthreads();
    for (int o = 128; o > 0; o >>= 1) {
        if (tid < o) s[tid] = fmaxf(s[tid], s[tid + o]);
        __syncthreads();
    }
    if (tid == 0) out[j] = scores[j] * expf(-SIGMA * s[0]);
}

// ---------------------------------------------------------------------------
extern "C" void kernel_launch(void* const* d_in, const int* in_sizes, int n_in,
                              void* d_out, int out_size) {
    const float* seg    = (const float*)d_in[0];
    const int*   labels = (const int*)d_in[1];
    const float* scores = (const float*)d_in[2];
    float* out = (float*)d_out;

    cudaFuncSetAttribute(gemm_kernel, cudaFuncAttributeMaxDynamicSharedMemorySize, SMEM_TOTAL);

    convert_kernel<<<N_DET, 256>>>(seg);
    gemm_kernel<<<NTILES * KSPLIT, 256, SMEM_TOTAL>>>();
    decay_kernel<<<N_DET, 256>>>(labels);
    colmax_kernel<<<N_DET, 256>>>();
    final_kernel<<<N_DET, 256>>>(scores, out);
}